// round 10
// baseline (speedup 1.0000x reference)
#include <cuda_runtime.h>
#include <cuda_fp16.h>
#include <cstdint>
#include <math.h>

// Problem constants: B=8, T=2048, D=2048, K=64
#define NROWS 16384
#define DDIM  2048
#define KDIM  64
#define THRESH 0.01f

// Scratch (allocation-free __device__ globals)
__device__ unsigned g_pH[KDIM * (DDIM / 2)];   // f16x2(p[2i], p[2i+1]) per k
__device__ float    g_pF[KDIM * DDIM];         // fp32 softmax(w) transposed [k][d]
__device__ float    g_nT[KDIM * DDIM];         // min-max normalized w cols, [k][d]
__device__ int      g_e[NROWS];                // argmax k (bits0..5) | neg (bit6)
__device__ int      g_nflag;                   // flagged-row count
__device__ int      g_frow[NROWS];             // flagged row ids
__device__ unsigned long long g_fmask[NROWS];  // candidate-k bitmasks

// ---------------------------------------------------------------------------
// helpers
// ---------------------------------------------------------------------------
__device__ __forceinline__ unsigned smem_u32(const void* p) {
    return (unsigned)__cvta_generic_to_shared(p);
}
__device__ __forceinline__ void cp16(void* dst, const void* src) {
    asm volatile("cp.async.cg.shared.global [%0], [%1], 16;\n"
                 :: "r"(smem_u32(dst)), "l"(src));
}
// m16n8k16 fp16 mma, fp32 acc, D += A*B (baseline PTX, sm_80+)
__device__ __forceinline__ void mma16(float* d, const unsigned* a, const unsigned* b) {
    asm volatile(
        "mma.sync.aligned.m16n8k16.row.col.f32.f16.f16.f32 "
        "{%0,%1,%2,%3}, {%4,%5,%6,%7}, {%8,%9}, {%0,%1,%2,%3};"
        : "+f"(d[0]), "+f"(d[1]), "+f"(d[2]), "+f"(d[3])
        : "r"(a[0]), "r"(a[1]), "r"(a[2]), "r"(a[3]), "r"(b[0]), "r"(b[1]));
}

// ---------------------------------------------------------------------------
// Kernel 1a: softmax of w rows (over K) in fp64; write fp32 transposed g_pF
// and fp16-hi packed g_pH. One warp per d-PAIR, 2 k per lane.
// ---------------------------------------------------------------------------
__global__ void prep_softmax(const float* __restrict__ w) {
    int gw = (blockIdx.x * blockDim.x + threadIdx.x) >> 5;   // d-pair id
    if (gw >= DDIM / 2) return;
    int lane = threadIdx.x & 31;
    int d0 = gw * 2, d1 = d0 + 1;
    float a0 = w[d0 * KDIM + lane], a1 = w[d0 * KDIM + lane + 32];
    float b0 = w[d1 * KDIM + lane], b1 = w[d1 * KDIM + lane + 32];
    float m0 = fmaxf(a0, a1), m1 = fmaxf(b0, b1);
#pragma unroll
    for (int off = 16; off; off >>= 1) {
        m0 = fmaxf(m0, __shfl_xor_sync(0xffffffffu, m0, off));
        m1 = fmaxf(m1, __shfl_xor_sync(0xffffffffu, m1, off));
    }
    double ea0 = exp((double)(a0 - m0)), ea1 = exp((double)(a1 - m0));
    double eb0 = exp((double)(b0 - m1)), eb1 = exp((double)(b1 - m1));
    double s0 = ea0 + ea1, s1 = eb0 + eb1;
#pragma unroll
    for (int off = 16; off; off >>= 1) {
        s0 += __shfl_xor_sync(0xffffffffu, s0, off);
        s1 += __shfl_xor_sync(0xffffffffu, s1, off);
    }
#pragma unroll
    for (int half = 0; half < 2; half++) {
        int k = lane + 32 * half;
        float p0 = (float)((half ? ea1 : ea0) / s0);
        float p1 = (float)((half ? eb1 : eb0) / s1);
        g_pF[k * DDIM + d0] = p0;
        g_pF[k * DDIM + d1] = p1;
        __half2 hp = __floats2half2_rn(p0, p1);          // low = d0
        g_pH[k * (DDIM / 2) + gw] = *reinterpret_cast<unsigned*>(&hp);
    }
}

// ---------------------------------------------------------------------------
// Kernel 1b: per-column min/max of w -> g_nT[k][d]; block 0 resets g_nflag.
// ---------------------------------------------------------------------------
__global__ void prep_norm(const float* __restrict__ w) {
    const int k = blockIdx.x;
    const int tid = threadIdx.x;
    if (k == 0 && tid == 0) g_nflag = 0;
    float mn = 3.402823466e38f, mx = -3.402823466e38f;
    for (int d = tid; d < DDIM; d += 256) {
        float v = w[d * KDIM + k];
        mn = fminf(mn, v);
        mx = fmaxf(mx, v);
    }
    __shared__ float smn[256], smx[256];
    smn[tid] = mn; smx[tid] = mx;
    __syncthreads();
    for (int s = 128; s; s >>= 1) {
        if (tid < s) {
            smn[tid] = fminf(smn[tid], smn[tid + s]);
            smx[tid] = fmaxf(smx[tid], smx[tid + s]);
        }
        __syncthreads();
    }
    mn = smn[0]; mx = smx[0];
    float inv = 1.f / (mx - mn);
    for (int d = tid; d < DDIM; d += 256)
        g_nT[k * DDIM + d] = (w[d * KDIM + k] - mn) * inv;
}

// ---------------------------------------------------------------------------
// Kernel 2: hi-only fp16 m16n8k16 scores + argmax + close-call flagging.
// 128 CTAs x (128 tok, 64 k). 8 warps, each 16 tok. 64 chunks of 32 dims.
// ---------------------------------------------------------------------------
#define XSTR 40                          // floats per x smem row
#define XB   (128 * XSTR * 4)            // 20480 B
#define PSTRU 20                         // uints per p smem row (16 data + 4 pad)
#define PB   (KDIM * PSTRU * 4)          // 5120 B
#define STG  (XB + PB)                   // 25600 B
#define SMEM_SZ (4 * STG)                // 102400 B

__global__ __launch_bounds__(256, 1) void score_kernel(const float* __restrict__ x) {
    extern __shared__ char sm[];
    const int tid = threadIdx.x;
    const int wid = tid >> 5, lane = tid & 31;
    const int lq = lane >> 2;            // 0..7
    const int lr = lane & 3;             // 0..3
    const float* xg = x + (size_t)blockIdx.x * 128 * DDIM;

    float acc[8][4];
#pragma unroll
    for (int nt = 0; nt < 8; nt++)
#pragma unroll
        for (int e = 0; e < 4; e++) acc[nt][e] = 0.f;

    auto prefetch = [&](int c) {
        char* base = sm + (size_t)(c & 3) * STG;
#pragma unroll
        for (int i = 0; i < 4; i++) {               // x: 128 rows x 32 floats
            int v = tid + 256 * i;
            int row = v >> 3, s = v & 7;
            cp16(base + row * (XSTR * 4) + s * 16,
                 xg + (size_t)row * DDIM + c * 32 + s * 4);
        }
        {                                           // p: 64 rows x 16 uints
            int k = tid >> 2, j = tid & 3;
            cp16(base + XB + k * (PSTRU * 4) + j * 16,
                 g_pH + (size_t)k * (DDIM / 2) + c * 16 + j * 4);
        }
        asm volatile("cp.async.commit_group;\n");
    };

    prefetch(0); prefetch(1); prefetch(2);

#pragma unroll 1
    for (int c = 0; c < 64; ++c) {
        if (c < 62)       asm volatile("cp.async.wait_group 2;\n");
        else if (c == 62) asm volatile("cp.async.wait_group 1;\n");
        else              asm volatile("cp.async.wait_group 0;\n");
        __syncthreads();
        if (c + 3 < 64) prefetch(c + 3);

        const char* base = sm + (size_t)(c & 3) * STG;
        const float* xs = (const float*)base;
        const unsigned* ps = (const unsigned*)(base + XB);

#pragma unroll
        for (int s = 0; s < 2; ++s) {               // two k16 steps per chunk
            unsigned ah[4];
#pragma unroll
            for (int pr = 0; pr < 4; pr++) {        // A: f32 pair -> fp16x2
                int row = wid * 16 + lq + (pr & 1) * 8;
                int dof = 16 * s + 2 * lr + (pr >> 1) * 8;
                float2 f = *reinterpret_cast<const float2*>(xs + row * XSTR + dof);
                __half2 h2 = __floats2half2_rn(f.x, f.y);
                ah[pr] = *reinterpret_cast<unsigned*>(&h2);
            }
            unsigned bh[8][2];
#pragma unroll
            for (int nt = 0; nt < 8; nt++) {        // B: plain f16x2 loads
                int k = nt * 8 + lq;
                bh[nt][0] = ps[k * PSTRU + 8 * s + lr];
                bh[nt][1] = ps[k * PSTRU + 8 * s + lr + 4];
            }
#pragma unroll
            for (int nt = 0; nt < 8; nt++)
                mma16(acc[nt], ah, bh[nt]);
        }
    }

    // Epilogue: rows wid*16 + h*8 + lq; cols nt*8 + 2*lr + j.
#pragma unroll
    for (int h = 0; h < 2; h++) {
        // local max + argmax (ascending k scan keeps first max)
        float bv = -3.402823466e38f; int bk = 0;
#pragma unroll
        for (int nt = 0; nt < 8; nt++)
#pragma unroll
            for (int j = 0; j < 2; j++) {
                float v = acc[nt][h * 2 + j];
                int k = nt * 8 + 2 * lr + j;
                if (v > bv) { bv = v; bk = k; }
            }
        float s1 = bv;
#pragma unroll
        for (int off = 1; off <= 2; off <<= 1)
            s1 = fmaxf(s1, __shfl_xor_sync(0xffffffffu, s1, off));
        // candidate mask: k with score > s1 - T
        unsigned long long mask = 0ull;
#pragma unroll
        for (int nt = 0; nt < 8; nt++)
#pragma unroll
            for (int j = 0; j < 2; j++) {
                float v = acc[nt][h * 2 + j];
                int k = nt * 8 + 2 * lr + j;
                if (v > s1 - THRESH) mask |= (1ull << k);
            }
#pragma unroll
        for (int off = 1; off <= 2; off <<= 1) {
            unsigned lo = (unsigned)mask, hi = (unsigned)(mask >> 32);
            lo |= __shfl_xor_sync(0xffffffffu, lo, off);
            hi |= __shfl_xor_sync(0xffffffffu, hi, off);
            mask = ((unsigned long long)hi << 32) | lo;
        }
        // combine argmax across quad (tie -> lowest k)
#pragma unroll
        for (int off = 1; off <= 2; off <<= 1) {
            float ov = __shfl_xor_sync(0xffffffffu, bv, off);
            int   ok = __shfl_xor_sync(0xffffffffu, bk, off);
            if (ov > bv || (ov == bv && ok < bk)) { bv = ov; bk = ok; }
        }
        if (lr == 0) {
            int row = blockIdx.x * 128 + wid * 16 + h * 8 + lq;
            g_e[row] = bk | (bv < 0.f ? 64 : 0);    // provisional
            if (__popcll(mask) > 1 || fabsf(s1) < THRESH) {
                int idx = atomicAdd(&g_nflag, 1);
                g_frow[idx] = row;
                g_fmask[idx] = mask;
            }
        }
    }
}

// ---------------------------------------------------------------------------
// Kernel 2b: fixup — exact fp32 dots for flagged rows' candidate k's.
// Fixed grid; one warp per flagged entry (strided).
// ---------------------------------------------------------------------------
__global__ __launch_bounds__(256) void fixup_kernel(const float* __restrict__ x) {
    const int n = g_nflag;
    const int nwarp = (gridDim.x * blockDim.x) >> 5;
    const int gw = (blockIdx.x * blockDim.x + threadIdx.x) >> 5;
    const int lane = threadIdx.x & 31;
    for (int e = gw; e < n; e += nwarp) {
        const int row = g_frow[e];
        unsigned long long mask = g_fmask[e];
        const float* xr = x + (size_t)row * DDIM;
        float bv = -3.402823466e38f; int bk = 0;
        while (mask) {
            int k = __ffsll((long long)mask) - 1;    // ascending k
            mask &= mask - 1;
            const float* pf = g_pF + (size_t)k * DDIM;
            float s = 0.f;
#pragma unroll 4
            for (int i = lane; i < DDIM; i += 32)
                s = fmaf(xr[i], pf[i], s);
#pragma unroll
            for (int off = 16; off; off >>= 1)
                s += __shfl_xor_sync(0xffffffffu, s, off);
            if (s > bv) { bv = s; bk = k; }          // strict > keeps lowest k
        }
        if (lane == 0) g_e[row] = bk | (bv < 0.f ? 64 : 0);
    }
}

// ---------------------------------------------------------------------------
// Kernel 3: out = x + x*W (R8 form: 1 row/CTA, measured 37.0 us).
// ---------------------------------------------------------------------------
__global__ __launch_bounds__(256) void out_kernel(const float* __restrict__ x,
                                                  float* __restrict__ out) {
    const long row = blockIdx.x;
    const int tid = threadIdx.x;
    const float4* xr = reinterpret_cast<const float4*>(x + row * DDIM);
    float4* orow = reinterpret_cast<float4*>(out + row * DDIM);
    if ((row & 2047) == 0) {          // t == 0 -> W = 0
        orow[tid] = xr[tid];
        orow[tid + 256] = xr[tid + 256];
        return;
    }
    const int e = g_e[row - 1];
    const float4* nr = reinterpret_cast<const float4*>(g_nT + (long)(e & 63) * DDIM);
    const bool neg = (e & 64) != 0;
#pragma unroll
    for (int it = 0; it < 2; ++it) {
        int i = tid + 256 * it;
        float4 xv = xr[i];
        float4 nv = nr[i];
        float wx = neg ? 1.f - nv.x : nv.x;
        float wy = neg ? 1.f - nv.y : nv.y;
        float wz = neg ? 1.f - nv.z : nv.z;
        float ww = neg ? 1.f - nv.w : nv.w;
        float4 o;
        o.x = fmaf(xv.x, wx, xv.x);
        o.y = fmaf(xv.y, wy, xv.y);
        o.z = fmaf(xv.z, wz, xv.z);
        o.w = fmaf(xv.w, ww, xv.w);
        orow[i] = o;
    }
}

// ---------------------------------------------------------------------------
extern "C" void kernel_launch(void* const* d_in, const int* in_sizes, int n_in,
                              void* d_out, int out_size) {
    const float* x = (const float*)d_in[0];
    const float* w = (const float*)d_in[1];
    if (n_in >= 2 && in_sizes[0] < in_sizes[1]) {
        const float* t = x; x = w; w = t;
    }
    cudaFuncSetAttribute(score_kernel,
                         cudaFuncAttributeMaxDynamicSharedMemorySize, SMEM_SZ);
    prep_softmax<<<128, 256>>>(w);           // 1024 warps = DDIM/2 d-pairs
    prep_norm<<<KDIM, 256>>>(w);
    score_kernel<<<NROWS / 128, 256, SMEM_SZ>>>(x);
    fixup_kernel<<<64, 256>>>(x);
    out_kernel<<<NROWS, 256>>>(x, (float*)d_out);
}

// round 13
// speedup vs baseline: 1.6345x; 1.6345x over previous
#include <cuda_runtime.h>
#include <cuda_fp16.h>
#include <cstdint>
#include <math.h>

// Problem constants: B=8, T=2048, D=2048, K=64
#define NROWS 16384
#define DDIM  2048
#define KDIM  64
#define THRESH 0.008f

// Scratch (allocation-free __device__ globals)
__device__ unsigned g_pH[KDIM * (DDIM / 2)];   // f16x2(p[2i], p[2i+1]) per k
__device__ float    g_pF[KDIM * DDIM];         // fp32 softmax(w) transposed [k][d]
__device__ float    g_nT[KDIM * DDIM];         // min-max normalized w cols, [k][d]
__device__ int      g_e[NROWS];                // argmax k (bits0..5) | neg (bit6)
__device__ int      g_nflag;                   // flagged-row count
__device__ int      g_frow[NROWS];             // flagged row ids
__device__ unsigned long long g_fmask[NROWS];  // candidate-k bitmasks

// ---------------------------------------------------------------------------
// helpers
// ---------------------------------------------------------------------------
__device__ __forceinline__ unsigned smem_u32(const void* p) {
    return (unsigned)__cvta_generic_to_shared(p);
}
__device__ __forceinline__ void cp16(void* dst, const void* src) {
    asm volatile("cp.async.cg.shared.global [%0], [%1], 16;\n"
                 :: "r"(smem_u32(dst)), "l"(src));
}
// m16n8k16 fp16 mma, fp32 acc, D += A*B (baseline PTX, sm_80+)
__device__ __forceinline__ void mma16(float* d, const unsigned* a, const unsigned* b) {
    asm volatile(
        "mma.sync.aligned.m16n8k16.row.col.f32.f16.f16.f32 "
        "{%0,%1,%2,%3}, {%4,%5,%6,%7}, {%8,%9}, {%0,%1,%2,%3};"
        : "+f"(d[0]), "+f"(d[1]), "+f"(d[2]), "+f"(d[3])
        : "r"(a[0]), "r"(a[1]), "r"(a[2]), "r"(a[3]), "r"(b[0]), "r"(b[1]));
}

// ---------------------------------------------------------------------------
// Kernel 1a: softmax of w rows (over K) in fp64; write fp32 transposed g_pF
// and fp16-hi packed g_pH. One warp per d-PAIR, 2 k per lane.
// ---------------------------------------------------------------------------
__global__ void prep_softmax(const float* __restrict__ w) {
    int gw = (blockIdx.x * blockDim.x + threadIdx.x) >> 5;   // d-pair id
    if (gw >= DDIM / 2) return;
    int lane = threadIdx.x & 31;
    int d0 = gw * 2, d1 = d0 + 1;
    float a0 = w[d0 * KDIM + lane], a1 = w[d0 * KDIM + lane + 32];
    float b0 = w[d1 * KDIM + lane], b1 = w[d1 * KDIM + lane + 32];
    float m0 = fmaxf(a0, a1), m1 = fmaxf(b0, b1);
#pragma unroll
    for (int off = 16; off; off >>= 1) {
        m0 = fmaxf(m0, __shfl_xor_sync(0xffffffffu, m0, off));
        m1 = fmaxf(m1, __shfl_xor_sync(0xffffffffu, m1, off));
    }
    double ea0 = exp((double)(a0 - m0)), ea1 = exp((double)(a1 - m0));
    double eb0 = exp((double)(b0 - m1)), eb1 = exp((double)(b1 - m1));
    double s0 = ea0 + ea1, s1 = eb0 + eb1;
#pragma unroll
    for (int off = 16; off; off >>= 1) {
        s0 += __shfl_xor_sync(0xffffffffu, s0, off);
        s1 += __shfl_xor_sync(0xffffffffu, s1, off);
    }
#pragma unroll
    for (int half = 0; half < 2; half++) {
        int k = lane + 32 * half;
        float p0 = (float)((half ? ea1 : ea0) / s0);
        float p1 = (float)((half ? eb1 : eb0) / s1);
        g_pF[k * DDIM + d0] = p0;
        g_pF[k * DDIM + d1] = p1;
        __half2 hp = __floats2half2_rn(p0, p1);          // low = d0
        g_pH[k * (DDIM / 2) + gw] = *reinterpret_cast<unsigned*>(&hp);
    }
}

// ---------------------------------------------------------------------------
// Kernel 1b: per-column min/max of w -> g_nT[k][d]; block 0 resets g_nflag.
// ---------------------------------------------------------------------------
__global__ void prep_norm(const float* __restrict__ w) {
    const int k = blockIdx.x;
    const int tid = threadIdx.x;
    if (k == 0 && tid == 0) g_nflag = 0;
    float mn = 3.402823466e38f, mx = -3.402823466e38f;
    for (int d = tid; d < DDIM; d += 256) {
        float v = w[d * KDIM + k];
        mn = fminf(mn, v);
        mx = fmaxf(mx, v);
    }
    __shared__ float smn[256], smx[256];
    smn[tid] = mn; smx[tid] = mx;
    __syncthreads();
    for (int s = 128; s; s >>= 1) {
        if (tid < s) {
            smn[tid] = fminf(smn[tid], smn[tid + s]);
            smx[tid] = fmaxf(smx[tid], smx[tid + s]);
        }
        __syncthreads();
    }
    mn = smn[0]; mx = smx[0];
    float inv = 1.f / (mx - mn);
    for (int d = tid; d < DDIM; d += 256)
        g_nT[k * DDIM + d] = (w[d * KDIM + k] - mn) * inv;
}

// ---------------------------------------------------------------------------
// Kernel 2: hi-only fp16 m16n8k16 scores + argmax + close-call flagging.
// 128 CTAs x (128 tok, 64 k). 8 warps, each 16 tok. 64 chunks of 32 dims.
// ---------------------------------------------------------------------------
#define XSTR 40                          // floats per x smem row
#define XB   (128 * XSTR * 4)            // 20480 B
#define PSTRU 20                         // uints per p smem row (16 data + 4 pad)
#define PB   (KDIM * PSTRU * 4)          // 5120 B
#define STG  (XB + PB)                   // 25600 B
#define SMEM_SZ (4 * STG)                // 102400 B

__global__ __launch_bounds__(256, 1) void score_kernel(const float* __restrict__ x) {
    extern __shared__ char sm[];
    const int tid = threadIdx.x;
    const int wid = tid >> 5, lane = tid & 31;
    const int lq = lane >> 2;            // 0..7
    const int lr = lane & 3;             // 0..3
    const float* xg = x + (size_t)blockIdx.x * 128 * DDIM;

    float acc[8][4];
#pragma unroll
    for (int nt = 0; nt < 8; nt++)
#pragma unroll
        for (int e = 0; e < 4; e++) acc[nt][e] = 0.f;

    auto prefetch = [&](int c) {
        char* base = sm + (size_t)(c & 3) * STG;
#pragma unroll
        for (int i = 0; i < 4; i++) {               // x: 128 rows x 32 floats
            int v = tid + 256 * i;
            int row = v >> 3, s = v & 7;
            cp16(base + row * (XSTR * 4) + s * 16,
                 xg + (size_t)row * DDIM + c * 32 + s * 4);
        }
        {                                           // p: 64 rows x 16 uints
            int k = tid >> 2, j = tid & 3;
            cp16(base + XB + k * (PSTRU * 4) + j * 16,
                 g_pH + (size_t)k * (DDIM / 2) + c * 16 + j * 4);
        }
        asm volatile("cp.async.commit_group;\n");
    };

    prefetch(0); prefetch(1); prefetch(2);

#pragma unroll 1
    for (int c = 0; c < 64; ++c) {
        if (c < 62)       asm volatile("cp.async.wait_group 2;\n");
        else if (c == 62) asm volatile("cp.async.wait_group 1;\n");
        else              asm volatile("cp.async.wait_group 0;\n");
        __syncthreads();
        if (c + 3 < 64) prefetch(c + 3);

        const char* base = sm + (size_t)(c & 3) * STG;
        const float* xs = (const float*)base;
        const unsigned* ps = (const unsigned*)(base + XB);

#pragma unroll
        for (int s = 0; s < 2; ++s) {               // two k16 steps per chunk
            unsigned ah[4];
#pragma unroll
            for (int pr = 0; pr < 4; pr++) {        // A: f32 pair -> fp16x2
                int row = wid * 16 + lq + (pr & 1) * 8;
                int dof = 16 * s + 2 * lr + (pr >> 1) * 8;
                float2 f = *reinterpret_cast<const float2*>(xs + row * XSTR + dof);
                __half2 h2 = __floats2half2_rn(f.x, f.y);
                ah[pr] = *reinterpret_cast<unsigned*>(&h2);
            }
            unsigned bh[8][2];
#pragma unroll
            for (int nt = 0; nt < 8; nt++) {        // B: plain f16x2 loads
                int k = nt * 8 + lq;
                bh[nt][0] = ps[k * PSTRU + 8 * s + lr];
                bh[nt][1] = ps[k * PSTRU + 8 * s + lr + 4];
            }
#pragma unroll
            for (int nt = 0; nt < 8; nt++)
                mma16(acc[nt], ah, bh[nt]);
        }
    }

    // Epilogue: rows wid*16 + h*8 + lq; cols nt*8 + 2*lr + j.
#pragma unroll
    for (int h = 0; h < 2; h++) {
        float bv = -3.402823466e38f; int bk = 0;
#pragma unroll
        for (int nt = 0; nt < 8; nt++)
#pragma unroll
            for (int j = 0; j < 2; j++) {
                float v = acc[nt][h * 2 + j];
                int k = nt * 8 + 2 * lr + j;
                if (v > bv) { bv = v; bk = k; }
            }
        float s1 = bv;
#pragma unroll
        for (int off = 1; off <= 2; off <<= 1)
            s1 = fmaxf(s1, __shfl_xor_sync(0xffffffffu, s1, off));
        unsigned long long mask = 0ull;
#pragma unroll
        for (int nt = 0; nt < 8; nt++)
#pragma unroll
            for (int j = 0; j < 2; j++) {
                float v = acc[nt][h * 2 + j];
                int k = nt * 8 + 2 * lr + j;
                if (v > s1 - THRESH) mask |= (1ull << k);
            }
#pragma unroll
        for (int off = 1; off <= 2; off <<= 1) {
            unsigned lo = (unsigned)mask, hi = (unsigned)(mask >> 32);
            lo |= __shfl_xor_sync(0xffffffffu, lo, off);
            hi |= __shfl_xor_sync(0xffffffffu, hi, off);
            mask = ((unsigned long long)hi << 32) | lo;
        }
#pragma unroll
        for (int off = 1; off <= 2; off <<= 1) {
            float ov = __shfl_xor_sync(0xffffffffu, bv, off);
            int   ok = __shfl_xor_sync(0xffffffffu, bk, off);
            if (ov > bv || (ov == bv && ok < bk)) { bv = ov; bk = ok; }
        }
        if (lr == 0) {
            int row = blockIdx.x * 128 + wid * 16 + h * 8 + lq;
            g_e[row] = bk | (bv < 0.f ? 64 : 0);    // provisional
            if (__popcll(mask) > 1 || fabsf(s1) < THRESH) {
                int idx = atomicAdd(&g_nflag, 1);
                g_frow[idx] = row;
                g_fmask[idx] = mask;
            }
        }
    }
}

// ---------------------------------------------------------------------------
// Kernel 2b: fixup v2 — one CTA per flagged row; x row staged in smem;
// one warp per candidate k, float4-strided dots (g_pF is L2-resident).
// ---------------------------------------------------------------------------
__global__ __launch_bounds__(256) void fixup_kernel(const float* __restrict__ x) {
    __shared__ float xs[DDIM];
    __shared__ int   ks[KDIM];
    __shared__ float sv[KDIM];
    const int n = g_nflag;
    const int tid = threadIdx.x, wid = tid >> 5, lane = tid & 31;
    for (int e = blockIdx.x; e < n; e += gridDim.x) {
        const int row = g_frow[e];
        if (tid == 0) {
            unsigned long long mask = g_fmask[e];
            int i = 0;
            while (mask) {                    // ascending k order
                ks[i++] = __ffsll((long long)mask) - 1;
                mask &= mask - 1;
            }
            ks[KDIM - 1] = i;                 // count in last slot (i <= 63 real ks)
        }
        const int cnt = __popcll(g_fmask[e]);
        const float4* xr = reinterpret_cast<const float4*>(x + (size_t)row * DDIM);
#pragma unroll
        for (int i = 0; i < 2; i++)
            reinterpret_cast<float4*>(xs)[tid + 256 * i] = xr[tid + 256 * i];
        __syncthreads();
        for (int c = wid; c < cnt; c += 8) {
            const float4* pf = reinterpret_cast<const float4*>(
                g_pF + (size_t)ks[c] * DDIM);
            const float4* xv4 = reinterpret_cast<const float4*>(xs);
            float s = 0.f;
#pragma unroll
            for (int i = 0; i < 16; i++) {
                float4 pv = pf[lane + 32 * i];
                float4 xv = xv4[lane + 32 * i];
                s = fmaf(xv.x, pv.x, s);
                s = fmaf(xv.y, pv.y, s);
                s = fmaf(xv.z, pv.z, s);
                s = fmaf(xv.w, pv.w, s);
            }
#pragma unroll
            for (int off = 16; off; off >>= 1)
                s += __shfl_xor_sync(0xffffffffu, s, off);
            if (lane == 0) sv[c] = s;
        }
        __syncthreads();
        if (tid == 0) {
            float bv = -3.402823466e38f; int bk = 0;
            for (int c = 0; c < cnt; c++)     // ks ascending -> strict > = first idx
                if (sv[c] > bv) { bv = sv[c]; bk = ks[c]; }
            g_e[row] = bk | (bv < 0.f ? 64 : 0);
        }
        __syncthreads();
    }
}

// ---------------------------------------------------------------------------
// Kernel 3: out = x + x*W (R8 form: 1 row/CTA, measured 37.0 us).
// ---------------------------------------------------------------------------
__global__ __launch_bounds__(256) void out_kernel(const float* __restrict__ x,
                                                  float* __restrict__ out) {
    const long row = blockIdx.x;
    const int tid = threadIdx.x;
    const float4* xr = reinterpret_cast<const float4*>(x + row * DDIM);
    float4* orow = reinterpret_cast<float4*>(out + row * DDIM);
    if ((row & 2047) == 0) {          // t == 0 -> W = 0
        orow[tid] = xr[tid];
        orow[tid + 256] = xr[tid + 256];
        return;
    }
    const int e = g_e[row - 1];
    const float4* nr = reinterpret_cast<const float4*>(g_nT + (long)(e & 63) * DDIM);
    const bool neg = (e & 64) != 0;
#pragma unroll
    for (int it = 0; it < 2; ++it) {
        int i = tid + 256 * it;
        float4 xv = xr[i];
        float4 nv = nr[i];
        float wx = neg ? 1.f - nv.x : nv.x;
        float wy = neg ? 1.f - nv.y : nv.y;
        float wz = neg ? 1.f - nv.z : nv.z;
        float ww = neg ? 1.f - nv.w : nv.w;
        float4 o;
        o.x = fmaf(xv.x, wx, xv.x);
        o.y = fmaf(xv.y, wy, xv.y);
        o.z = fmaf(xv.z, wz, xv.z);
        o.w = fmaf(xv.w, ww, xv.w);
        orow[i] = o;
    }
}

// ---------------------------------------------------------------------------
extern "C" void kernel_launch(void* const* d_in, const int* in_sizes, int n_in,
                              void* d_out, int out_size) {
    const float* x = (const float*)d_in[0];
    const float* w = (const float*)d_in[1];
    if (n_in >= 2 && in_sizes[0] < in_sizes[1]) {
        const float* t = x; x = w; w = t;
    }
    cudaFuncSetAttribute(score_kernel,
                         cudaFuncAttributeMaxDynamicSharedMemorySize, SMEM_SZ);
    prep_softmax<<<128, 256>>>(w);           // 1024 warps = DDIM/2 d-pairs
    prep_norm<<<KDIM, 256>>>(w);
    score_kernel<<<NROWS / 128, 256, SMEM_SZ>>>(x);
    fixup_kernel<<<512, 256>>>(x);
    out_kernel<<<NROWS, 256>>>(x, (float*)d_out);
}

// round 14
// speedup vs baseline: 1.8195x; 1.1132x over previous
#include <cuda_runtime.h>
#include <cuda_fp16.h>
#include <cstdint>
#include <math.h>

// Problem constants: B=8, T=2048, D=2048, K=64
#define NROWS 16384
#define DDIM  2048
#define KDIM  64
#define THRESH 0.005f

// Scratch (allocation-free __device__ globals)
__device__ unsigned g_pH[KDIM * (DDIM / 2)];   // f16x2(p[2i], p[2i+1]) per k
__device__ float    g_pF[KDIM * DDIM];         // fp32 softmax(w) transposed [k][d]
__device__ float    g_nT[KDIM * DDIM];         // min-max normalized w cols, [k][d]
__device__ int      g_e[NROWS];                // argmax k (bits0..5) | neg (bit6)
__device__ int      g_nflag;                   // flagged-row count
__device__ int      g_frow[NROWS];             // flagged row ids
__device__ unsigned long long g_fmask[NROWS];  // candidate-k bitmasks

// ---------------------------------------------------------------------------
// helpers
// ---------------------------------------------------------------------------
__device__ __forceinline__ unsigned smem_u32(const void* p) {
    return (unsigned)__cvta_generic_to_shared(p);
}
__device__ __forceinline__ void cp16(void* dst, const void* src) {
    asm volatile("cp.async.cg.shared.global [%0], [%1], 16;\n"
                 :: "r"(smem_u32(dst)), "l"(src));
}
// m16n8k16 fp16 mma, fp32 acc, D += A*B (baseline PTX, sm_80+)
__device__ __forceinline__ void mma16(float* d, const unsigned* a, const unsigned* b) {
    asm volatile(
        "mma.sync.aligned.m16n8k16.row.col.f32.f16.f16.f32 "
        "{%0,%1,%2,%3}, {%4,%5,%6,%7}, {%8,%9}, {%0,%1,%2,%3};"
        : "+f"(d[0]), "+f"(d[1]), "+f"(d[2]), "+f"(d[3])
        : "r"(a[0]), "r"(a[1]), "r"(a[2]), "r"(a[3]), "r"(b[0]), "r"(b[1]));
}

// ---------------------------------------------------------------------------
// Kernel 1a: softmax of w rows (over K) in fp32 (expf ~1ulp, matches the
// reference's own fp32 softmax); write fp32 transposed g_pF and fp16-hi
// packed g_pH. One warp per d-PAIR, 2 k per lane.
// ---------------------------------------------------------------------------
__global__ void prep_softmax(const float* __restrict__ w) {
    int gw = (blockIdx.x * blockDim.x + threadIdx.x) >> 5;   // d-pair id
    if (gw >= DDIM / 2) return;
    int lane = threadIdx.x & 31;
    int d0 = gw * 2, d1 = d0 + 1;
    float a0 = w[d0 * KDIM + lane], a1 = w[d0 * KDIM + lane + 32];
    float b0 = w[d1 * KDIM + lane], b1 = w[d1 * KDIM + lane + 32];
    float m0 = fmaxf(a0, a1), m1 = fmaxf(b0, b1);
#pragma unroll
    for (int off = 16; off; off >>= 1) {
        m0 = fmaxf(m0, __shfl_xor_sync(0xffffffffu, m0, off));
        m1 = fmaxf(m1, __shfl_xor_sync(0xffffffffu, m1, off));
    }
    float ea0 = expf(a0 - m0), ea1 = expf(a1 - m0);
    float eb0 = expf(b0 - m1), eb1 = expf(b1 - m1);
    float s0 = ea0 + ea1, s1 = eb0 + eb1;
#pragma unroll
    for (int off = 16; off; off >>= 1) {
        s0 += __shfl_xor_sync(0xffffffffu, s0, off);
        s1 += __shfl_xor_sync(0xffffffffu, s1, off);
    }
    float r0 = 1.f / s0, r1 = 1.f / s1;
#pragma unroll
    for (int half = 0; half < 2; half++) {
        int k = lane + 32 * half;
        float p0 = (half ? ea1 : ea0) * r0;
        float p1 = (half ? eb1 : eb0) * r1;
        g_pF[k * DDIM + d0] = p0;
        g_pF[k * DDIM + d1] = p1;
        __half2 hp = __floats2half2_rn(p0, p1);          // low = d0
        g_pH[k * (DDIM / 2) + gw] = *reinterpret_cast<unsigned*>(&hp);
    }
}

// ---------------------------------------------------------------------------
// Kernel 1b: per-column min/max of w -> g_nT[k][d]. 1024 threads per CTA
// (2 elems/thread) for 4x the latency hiding. Block 0 resets g_nflag.
// ---------------------------------------------------------------------------
__global__ __launch_bounds__(1024) void prep_norm(const float* __restrict__ w) {
    const int k = blockIdx.x;
    const int tid = threadIdx.x;
    if (k == 0 && tid == 0) g_nflag = 0;
    float v0 = w[tid * KDIM + k];
    float v1 = w[(tid + 1024) * KDIM + k];
    float mn = fminf(v0, v1), mx = fmaxf(v0, v1);
    __shared__ float smn[1024], smx[1024];
    smn[tid] = mn; smx[tid] = mx;
    __syncthreads();
    for (int s = 512; s; s >>= 1) {
        if (tid < s) {
            smn[tid] = fminf(smn[tid], smn[tid + s]);
            smx[tid] = fmaxf(smx[tid], smx[tid + s]);
        }
        __syncthreads();
    }
    mn = smn[0]; mx = smx[0];
    float inv = 1.f / (mx - mn);
    g_nT[k * DDIM + tid]        = (v0 - mn) * inv;
    g_nT[k * DDIM + tid + 1024] = (v1 - mn) * inv;
}

// ---------------------------------------------------------------------------
// Kernel 2: hi-only fp16 m16n8k16 scores + argmax + close-call flagging.
// 128 CTAs x (128 tok, 64 k). 8 warps, each 16 tok. 64 chunks of 32 dims.
// ---------------------------------------------------------------------------
#define XSTR 40                          // floats per x smem row
#define XB   (128 * XSTR * 4)            // 20480 B
#define PSTRU 20                         // uints per p smem row (16 data + 4 pad)
#define PB   (KDIM * PSTRU * 4)          // 5120 B
#define STG  (XB + PB)                   // 25600 B
#define SMEM_SZ (4 * STG)                // 102400 B

__global__ __launch_bounds__(256, 1) void score_kernel(const float* __restrict__ x) {
    extern __shared__ char sm[];
    const int tid = threadIdx.x;
    const int wid = tid >> 5, lane = tid & 31;
    const int lq = lane >> 2;            // 0..7
    const int lr = lane & 3;             // 0..3
    const float* xg = x + (size_t)blockIdx.x * 128 * DDIM;

    float acc[8][4];
#pragma unroll
    for (int nt = 0; nt < 8; nt++)
#pragma unroll
        for (int e = 0; e < 4; e++) acc[nt][e] = 0.f;

    auto prefetch = [&](int c) {
        char* base = sm + (size_t)(c & 3) * STG;
#pragma unroll
        for (int i = 0; i < 4; i++) {               // x: 128 rows x 32 floats
            int v = tid + 256 * i;
            int row = v >> 3, s = v & 7;
            cp16(base + row * (XSTR * 4) + s * 16,
                 xg + (size_t)row * DDIM + c * 32 + s * 4);
        }
        {                                           // p: 64 rows x 16 uints
            int k = tid >> 2, j = tid & 3;
            cp16(base + XB + k * (PSTRU * 4) + j * 16,
                 g_pH + (size_t)k * (DDIM / 2) + c * 16 + j * 4);
        }
        asm volatile("cp.async.commit_group;\n");
    };

    prefetch(0); prefetch(1); prefetch(2);

#pragma unroll 1
    for (int c = 0; c < 64; ++c) {
        if (c < 62)       asm volatile("cp.async.wait_group 2;\n");
        else if (c == 62) asm volatile("cp.async.wait_group 1;\n");
        else              asm volatile("cp.async.wait_group 0;\n");
        __syncthreads();
        if (c + 3 < 64) prefetch(c + 3);

        const char* base = sm + (size_t)(c & 3) * STG;
        const float* xs = (const float*)base;
        const unsigned* ps = (const unsigned*)(base + XB);

#pragma unroll
        for (int s = 0; s < 2; ++s) {               // two k16 steps per chunk
            unsigned ah[4];
#pragma unroll
            for (int pr = 0; pr < 4; pr++) {        // A: f32 pair -> fp16x2
                int row = wid * 16 + lq + (pr & 1) * 8;
                int dof = 16 * s + 2 * lr + (pr >> 1) * 8;
                float2 f = *reinterpret_cast<const float2*>(xs + row * XSTR + dof);
                __half2 h2 = __floats2half2_rn(f.x, f.y);
                ah[pr] = *reinterpret_cast<unsigned*>(&h2);
            }
            unsigned bh[8][2];
#pragma unroll
            for (int nt = 0; nt < 8; nt++) {        // B: plain f16x2 loads
                int k = nt * 8 + lq;
                bh[nt][0] = ps[k * PSTRU + 8 * s + lr];
                bh[nt][1] = ps[k * PSTRU + 8 * s + lr + 4];
            }
#pragma unroll
            for (int nt = 0; nt < 8; nt++)
                mma16(acc[nt], ah, bh[nt]);
        }
    }

    // Epilogue: rows wid*16 + h*8 + lq; cols nt*8 + 2*lr + j.
#pragma unroll
    for (int h = 0; h < 2; h++) {
        float bv = -3.402823466e38f; int bk = 0;
#pragma unroll
        for (int nt = 0; nt < 8; nt++)
#pragma unroll
            for (int j = 0; j < 2; j++) {
                float v = acc[nt][h * 2 + j];
                int k = nt * 8 + 2 * lr + j;
                if (v > bv) { bv = v; bk = k; }
            }
        float s1 = bv;
#pragma unroll
        for (int off = 1; off <= 2; off <<= 1)
            s1 = fmaxf(s1, __shfl_xor_sync(0xffffffffu, s1, off));
        unsigned long long mask = 0ull;
#pragma unroll
        for (int nt = 0; nt < 8; nt++)
#pragma unroll
            for (int j = 0; j < 2; j++) {
                float v = acc[nt][h * 2 + j];
                int k = nt * 8 + 2 * lr + j;
                if (v > s1 - THRESH) mask |= (1ull << k);
            }
#pragma unroll
        for (int off = 1; off <= 2; off <<= 1) {
            unsigned lo = (unsigned)mask, hi = (unsigned)(mask >> 32);
            lo |= __shfl_xor_sync(0xffffffffu, lo, off);
            hi |= __shfl_xor_sync(0xffffffffu, hi, off);
            mask = ((unsigned long long)hi << 32) | lo;
        }
#pragma unroll
        for (int off = 1; off <= 2; off <<= 1) {
            float ov = __shfl_xor_sync(0xffffffffu, bv, off);
            int   ok = __shfl_xor_sync(0xffffffffu, bk, off);
            if (ov > bv || (ov == bv && ok < bk)) { bv = ov; bk = ok; }
        }
        if (lr == 0) {
            int row = blockIdx.x * 128 + wid * 16 + h * 8 + lq;
            g_e[row] = bk | (bv < 0.f ? 64 : 0);    // provisional
            if (__popcll(mask) > 1 || fabsf(s1) < THRESH) {
                int idx = atomicAdd(&g_nflag, 1);
                g_frow[idx] = row;
                g_fmask[idx] = mask;
            }
        }
    }
}

// ---------------------------------------------------------------------------
// Kernel 2b: fixup — one CTA per flagged row; x row staged in smem;
// one warp per candidate k, float4-strided dots (g_pF is L2-resident).
// ---------------------------------------------------------------------------
__global__ __launch_bounds__(256) void fixup_kernel(const float* __restrict__ x) {
    __shared__ float xs[DDIM];
    __shared__ int   ks[KDIM];
    __shared__ float sv[KDIM];
    const int n = g_nflag;
    const int tid = threadIdx.x, wid = tid >> 5, lane = tid & 31;
    for (int e = blockIdx.x; e < n; e += gridDim.x) {
        const int row = g_frow[e];
        if (tid == 0) {
            unsigned long long mask = g_fmask[e];
            int i = 0;
            while (mask) {                    // ascending k order
                ks[i++] = __ffsll((long long)mask) - 1;
                mask &= mask - 1;
            }
        }
        const int cnt = __popcll(g_fmask[e]);
        const float4* xr = reinterpret_cast<const float4*>(x + (size_t)row * DDIM);
#pragma unroll
        for (int i = 0; i < 2; i++)
            reinterpret_cast<float4*>(xs)[tid + 256 * i] = xr[tid + 256 * i];
        __syncthreads();
        for (int c = wid; c < cnt; c += 8) {
            const float4* pf = reinterpret_cast<const float4*>(
                g_pF + (size_t)ks[c] * DDIM);
            const float4* xv4 = reinterpret_cast<const float4*>(xs);
            float s = 0.f;
#pragma unroll
            for (int i = 0; i < 16; i++) {
                float4 pv = pf[lane + 32 * i];
                float4 xv = xv4[lane + 32 * i];
                s = fmaf(xv.x, pv.x, s);
                s = fmaf(xv.y, pv.y, s);
                s = fmaf(xv.z, pv.z, s);
                s = fmaf(xv.w, pv.w, s);
            }
#pragma unroll
            for (int off = 16; off; off >>= 1)
                s += __shfl_xor_sync(0xffffffffu, s, off);
            if (lane == 0) sv[c] = s;
        }
        __syncthreads();
        if (tid == 0) {
            float bv = -3.402823466e38f; int bk = 0;
            for (int c = 0; c < cnt; c++)     // ks ascending -> strict > = first idx
                if (sv[c] > bv) { bv = sv[c]; bk = ks[c]; }
            g_e[row] = bk | (bv < 0.f ? 64 : 0);
        }
        __syncthreads();
    }
}

// ---------------------------------------------------------------------------
// Kernel 3: out = x + x*W (1 row/CTA, measured 37.0 us / 73% DRAM).
// ---------------------------------------------------------------------------
__global__ __launch_bounds__(256) void out_kernel(const float* __restrict__ x,
                                                  float* __restrict__ out) {
    const long row = blockIdx.x;
    const int tid = threadIdx.x;
    const float4* xr = reinterpret_cast<const float4*>(x + row * DDIM);
    float4* orow = reinterpret_cast<float4*>(out + row * DDIM);
    if ((row & 2047) == 0) {          // t == 0 -> W = 0
        orow[tid] = xr[tid];
        orow[tid + 256] = xr[tid + 256];
        return;
    }
    const int e = g_e[row - 1];
    const float4* nr = reinterpret_cast<const float4*>(g_nT + (long)(e & 63) * DDIM);
    const bool neg = (e & 64) != 0;
#pragma unroll
    for (int it = 0; it < 2; ++it) {
        int i = tid + 256 * it;
        float4 xv = xr[i];
        float4 nv = nr[i];
        float wx = neg ? 1.f - nv.x : nv.x;
        float wy = neg ? 1.f - nv.y : nv.y;
        float wz = neg ? 1.f - nv.z : nv.z;
        float ww = neg ? 1.f - nv.w : nv.w;
        float4 o;
        o.x = fmaf(xv.x, wx, xv.x);
        o.y = fmaf(xv.y, wy, xv.y);
        o.z = fmaf(xv.z, wz, xv.z);
        o.w = fmaf(xv.w, ww, xv.w);
        orow[i] = o;
    }
}

// ---------------------------------------------------------------------------
extern "C" void kernel_launch(void* const* d_in, const int* in_sizes, int n_in,
                              void* d_out, int out_size) {
    const float* x = (const float*)d_in[0];
    const float* w = (const float*)d_in[1];
    if (n_in >= 2 && in_sizes[0] < in_sizes[1]) {
        const float* t = x; x = w; w = t;
    }
    cudaFuncSetAttribute(score_kernel,
                         cudaFuncAttributeMaxDynamicSharedMemorySize, SMEM_SZ);
    prep_softmax<<<128, 256>>>(w);           // 1024 warps = DDIM/2 d-pairs
    prep_norm<<<KDIM, 1024>>>(w);
    score_kernel<<<NROWS / 128, 256, SMEM_SZ>>>(x);
    fixup_kernel<<<2048, 256>>>(x);
    out_kernel<<<NROWS, 256>>>(x, (float*)d_out);
}